// round 6
// baseline (speedup 1.0000x reference)
#include <cuda_runtime.h>
#include <stdint.h>

typedef unsigned long long u64;

#define IN_CH     128
#define OC        64
#define MAX_NODES 100000
#define BM        128
#define KC        32
#define XSTR      132   // floats per k-row: 128 + 4 pad (multiple of 4 -> 16B-aligned quads)

__device__ unsigned int g_mask[MAX_NODES];
__device__ int          g_is64;

// Zero the mask; block 0 / warp 0 also detects edge_index dtype.
// int64 view of int64 data: ids < 1e5 -> every odd 32-bit word (high half) is 0.
__global__ void k_zero_detect(int n, const unsigned int* __restrict__ ei32) {
    int i = blockIdx.x * blockDim.x + threadIdx.x;
    if (i < n) g_mask[i] = 0u;
    if (blockIdx.x == 0 && threadIdx.x < 32) {
        unsigned int w = 0;
        #pragma unroll
        for (int j = threadIdx.x; j < 128; j += 32) w |= ei32[2 * j + 1];
        unsigned int any = __ballot_sync(0xffffffffu, w != 0u);
        if (threadIdx.x == 0) g_is64 = (any == 0u) ? 1 : 0;
    }
}

// Scatter "has incoming edge", 2 edges per thread, bounds-clamped.
__global__ void k_scatter_mask(const long long* __restrict__ col64,
                               const int* __restrict__ col32,
                               int ne, int n) {
    int i = (blockIdx.x * blockDim.x + threadIdx.x) * 2;
    if (i >= ne) return;
    const int is64 = g_is64;
    long long v0, v1;
    if (is64) {
        longlong2 p = *reinterpret_cast<const longlong2*>(col64 + i);
        v0 = p.x; v1 = p.y;
    } else {
        int2 p = *reinterpret_cast<const int2*>(col32 + i);
        v0 = p.x; v1 = p.y;
    }
    if (v0 >= 0 && v0 < n) g_mask[(int)v0] = 1u;
    if (i + 1 < ne && v1 >= 0 && v1 < n) g_mask[(int)v1] = 1u;
}

__device__ __forceinline__ u64 ffma2(u64 a, u64 b, u64 c) {
    u64 d;
    asm("fma.rn.f32x2 %0, %1, %2, %3;" : "=l"(d) : "l"(a), "l"(b), "l"(c));
    return d;
}
__device__ __forceinline__ u64 dup2(float a) {
    u64 d;
    asm("mov.b64 %0, {%1, %1};" : "=l"(d) : "f"(a));
    return d;
}

// out[r,:] = mask[r] ? x[r,:] @ W : 0
// 256 threads; tile BM=128 rows x OC=64 cols.
// Thread (tx = tid&7 -> cols tx*8..tx*8+7; trow = tid>>3 -> rows trow*4..trow*4+3).
// acc[l][j] packs output cols (8tx+2j, 8tx+2j+1) for row trow*4+l as one f32x2.
// Per k: 1 LDS.128 (x quad) + 2 LDS.128 (W, natural layout, lane-broadcast)
//        + 4 dup2 + 16 FFMA2  -> FMA-pipe bound.
__global__ __launch_bounds__(256, 3) void k_gemm_mask(
    const float* __restrict__ x,
    const float* __restrict__ W,
    float* __restrict__ out,
    int n)
{
    __shared__ __align__(16) float xs[KC * XSTR];  // transposed x: xs[k][row]
    __shared__ __align__(16) u64   ws[KC * 32];    // W chunk verbatim: ws[k][c/2]

    const int tid  = threadIdx.x;
    const int tx   = tid & 7;
    const int trow = tid >> 3;        // 0..31
    const int row0 = blockIdx.x * BM;

    u64 acc[4][4];
    #pragma unroll
    for (int l = 0; l < 4; l++)
        #pragma unroll
        for (int j = 0; j < 4; j++)
            acc[l][j] = 0ull;

    #pragma unroll 1
    for (int kc = 0; kc < IN_CH; kc += KC) {
        // ---- stage x tile transposed (coalesced 128B global segments per warp)
        #pragma unroll
        for (int jj = 0; jj < 4; jj++) {
            int f    = tid + jj * 256;   // float4 id, 0..1023
            int r    = f >> 3;           // local row 0..127
            int c4   = f & 7;            // k sub-quad
            int grow = row0 + r;
            float4 v = make_float4(0.f, 0.f, 0.f, 0.f);
            if (grow < n)
                v = *reinterpret_cast<const float4*>(x + (size_t)grow * IN_CH + kc + c4 * 4);
            xs[(c4 * 4 + 0) * XSTR + r] = v.x;
            xs[(c4 * 4 + 1) * XSTR + r] = v.y;
            xs[(c4 * 4 + 2) * XSTR + r] = v.z;
            xs[(c4 * 4 + 3) * XSTR + r] = v.w;
        }
        // ---- stage W chunk verbatim (contiguous 8KB)
        {
            const float4* src = reinterpret_cast<const float4*>(W + kc * OC);
            float4*       dst = reinterpret_cast<float4*>(ws);
            dst[tid]       = src[tid];
            dst[tid + 256] = src[tid + 256];
        }
        __syncthreads();

        // ---- mainloop
        #pragma unroll 8
        for (int k = 0; k < KC; k++) {
            float4 xv = *reinterpret_cast<const float4*>(xs + k * XSTR + trow * 4);
            u64 xd[4];
            xd[0] = dup2(xv.x); xd[1] = dup2(xv.y);
            xd[2] = dup2(xv.z); xd[3] = dup2(xv.w);

            const ulonglong2* wp = reinterpret_cast<const ulonglong2*>(ws + k * 32 + tx * 4);
            ulonglong2 w01 = wp[0];   // cols 8tx..8tx+3
            ulonglong2 w23 = wp[1];   // cols 8tx+4..8tx+7

            #pragma unroll
            for (int l = 0; l < 4; l++) {
                acc[l][0] = ffma2(xd[l], w01.x, acc[l][0]);
                acc[l][1] = ffma2(xd[l], w01.y, acc[l][1]);
                acc[l][2] = ffma2(xd[l], w23.x, acc[l][2]);
                acc[l][3] = ffma2(xd[l], w23.y, acc[l][3]);
            }
        }
        __syncthreads();
    }

    // ---- epilogue: per row, mask + 2 float4 stores
    #pragma unroll
    for (int l = 0; l < 4; l++) {
        int r = row0 + trow * 4 + l;
        if (r >= n) continue;
        float m = g_mask[r] ? 1.0f : 0.0f;
        float o[8];
        #pragma unroll
        for (int j = 0; j < 4; j++) {
            u64 p = acc[l][j];
            o[2*j]   = __uint_as_float((unsigned int)p) * m;
            o[2*j+1] = __uint_as_float((unsigned int)(p >> 32)) * m;
        }
        float4* po = reinterpret_cast<float4*>(out + (size_t)r * OC + tx * 8);
        po[0] = make_float4(o[0], o[1], o[2], o[3]);
        po[1] = make_float4(o[4], o[5], o[6], o[7]);
    }
}

extern "C" void kernel_launch(void* const* d_in, const int* in_sizes, int n_in,
                              void* d_out, int out_size)
{
    // metadata order: x, edge_index, edge_attr, W, W_edge, a
    const float* x   = (const float*)d_in[0];
    const void*  ei  = d_in[1];                 // int64 or int32 [2, E], detected on device
    const float* W   = (const float*)d_in[3];   // [128, 64] row-major
    float*       out = (float*)d_out;

    const int n  = in_sizes[0] / IN_CH;   // 100000
    const int ne = in_sizes[1] / 2;       // 1600000

    const long long* col64 = (const long long*)ei + ne;
    const int*       col32 = (const int*)ei + ne;

    k_zero_detect <<<(n + 255) / 256, 256>>>(n, (const unsigned int*)ei);
    k_scatter_mask<<<(ne / 2 + 255) / 256, 256>>>(col64, col32, ne, n);
    k_gemm_mask   <<<(n + BM - 1) / BM, 256>>>(x, W, out, n);
}

// round 7
// speedup vs baseline: 1.2390x; 1.2390x over previous
#include <cuda_runtime.h>
#include <stdint.h>

typedef unsigned long long u64;

#define IN_CH     128
#define OC        64
#define MAX_NODES 100000
#define BM        128
#define KC        32
#define XSTR      130   // 128 + 2 pad; ≡2 mod 32 → 2-way STS staging, conflict-free float2 LDS

__device__ unsigned int g_mask[MAX_NODES];
__device__ int          g_is64;

// Detect int64 vs int32 edge_index: int64 view has all-zero high words (ids < 1e5).
__global__ void k_detect(const unsigned int* __restrict__ ei32) {
    unsigned int w = 0;
    #pragma unroll
    for (int i = threadIdx.x; i < 128; i += 32) w |= ei32[2 * i + 1];
    unsigned int any = __ballot_sync(0xffffffffu, w != 0u);
    if (threadIdx.x == 0) g_is64 = (any == 0u) ? 1 : 0;
}

__global__ void k_zero_mask(int n) {
    int i = blockIdx.x * blockDim.x + threadIdx.x;
    if (i < n) g_mask[i] = 0u;
}

__global__ void k_scatter_mask(const long long* __restrict__ col64,
                               const int* __restrict__ col32,
                               int ne, int n) {
    int i = blockIdx.x * blockDim.x + threadIdx.x;
    if (i >= ne) return;
    long long v = g_is64 ? col64[i] : (long long)col32[i];
    if (v >= 0 && v < (long long)n) g_mask[(int)v] = 1u;
}

__device__ __forceinline__ u64 ffma2(u64 a, u64 b, u64 c) {
    u64 d;
    asm("fma.rn.f32x2 %0, %1, %2, %3;" : "=l"(d) : "l"(a), "l"(b), "l"(c));
    return d;
}
__device__ __forceinline__ u64 dup2(float a) {
    u64 d;
    asm("mov.b64 %0, {%1, %1};" : "=l"(d) : "f"(a));
    return d;
}

// out[r,:] = mask[r] ? x[r,:] @ W : 0
// 256 threads; tile BM=128 rows x OC=64 cols.
// Warp w = tid>>5: col-group cgi = w&3 (cols cgi*16..+15, UNIFORM per warp ->
// every W LDS is a single-address broadcast), row-pair rp = (w>>2)*32 + lane
// (consecutive lanes -> conflict-free x LDS.64). Thread tile: 2 rows x 16 cols.
// acc[row][j] packs output cols (16cgi+2j, 16cgi+2j+1) as one f32x2.
__global__ __launch_bounds__(256, 3) void k_gemm_mask(
    const float* __restrict__ x,
    const float* __restrict__ W,
    float* __restrict__ out,
    int n)
{
    __shared__ __align__(16) float xs[KC * XSTR];  // transposed x: xs[k][row]
    __shared__ __align__(16) u64   ws[KC * 32];    // W chunk verbatim: ws[k][c/2]

    const int tid  = threadIdx.x;
    const int w    = tid >> 5;
    const int lane = tid & 31;
    const int cgi  = w & 3;                 // column group (uniform per warp)
    const int rp   = ((w >> 2) << 5) + lane; // row pair 0..63
    const int row0 = blockIdx.x * BM;

    u64 acc0[8], acc1[8];
    #pragma unroll
    for (int j = 0; j < 8; j++) { acc0[j] = 0ull; acc1[j] = 0ull; }

    #pragma unroll 1
    for (int kc = 0; kc < IN_CH; kc += KC) {
        // ---- stage x tile transposed (coalesced 128B global segments per warp)
        #pragma unroll
        for (int jj = 0; jj < 4; jj++) {
            int f    = tid + jj * 256;   // float4 id, 0..1023
            int r    = f >> 3;           // local row 0..127
            int c4   = f & 7;            // k sub-quad
            int grow = row0 + r;
            float4 v = make_float4(0.f, 0.f, 0.f, 0.f);
            if (grow < n)
                v = *reinterpret_cast<const float4*>(x + (size_t)grow * IN_CH + kc + c4 * 4);
            xs[(c4 * 4 + 0) * XSTR + r] = v.x;
            xs[(c4 * 4 + 1) * XSTR + r] = v.y;
            xs[(c4 * 4 + 2) * XSTR + r] = v.z;
            xs[(c4 * 4 + 3) * XSTR + r] = v.w;
        }
        // ---- stage W chunk verbatim (contiguous 8KB)
        {
            const float4* src = reinterpret_cast<const float4*>(W + kc * OC);
            float4*       dst = reinterpret_cast<float4*>(ws);
            dst[tid]       = src[tid];
            dst[tid + 256] = src[tid + 256];
        }
        __syncthreads();

        // ---- mainloop: per k: 1 LDS.64 (x) + 4 LDS.128 (W bcast) + 2 dup2 + 16 FFMA2
        #pragma unroll 4
        for (int k = 0; k < KC; k++) {
            float2 xv = *reinterpret_cast<const float2*>(xs + k * XSTR + 2 * rp);
            u64 x0 = dup2(xv.x);
            u64 x1 = dup2(xv.y);
            const ulonglong2* wp = reinterpret_cast<const ulonglong2*>(ws + k * 32 + cgi * 8);
            #pragma unroll
            for (int q = 0; q < 4; q++) {
                ulonglong2 wv = wp[q];     // col pairs 2q, 2q+1 of this group
                acc0[2*q]   = ffma2(x0, wv.x, acc0[2*q]);
                acc0[2*q+1] = ffma2(x0, wv.y, acc0[2*q+1]);
                acc1[2*q]   = ffma2(x1, wv.x, acc1[2*q]);
                acc1[2*q+1] = ffma2(x1, wv.y, acc1[2*q+1]);
            }
        }
        __syncthreads();
    }

    // ---- epilogue: 2 rows, mask + 4 float4 stores per row
    const int r0 = row0 + 2 * rp;
    const int r1 = r0 + 1;
    const float m0 = (r0 < n && g_mask[r0]) ? 1.0f : 0.0f;
    const float m1 = (r1 < n && g_mask[r1]) ? 1.0f : 0.0f;

    #pragma unroll
    for (int q = 0; q < 4; q++) {
        if (r0 < n) {
            u64 pa = acc0[2*q], pb = acc0[2*q+1];
            *reinterpret_cast<float4*>(out + (size_t)r0 * OC + cgi * 16 + 4 * q) =
                make_float4(__uint_as_float((unsigned int)pa) * m0,
                            __uint_as_float((unsigned int)(pa >> 32)) * m0,
                            __uint_as_float((unsigned int)pb) * m0,
                            __uint_as_float((unsigned int)(pb >> 32)) * m0);
        }
        if (r1 < n) {
            u64 pa = acc1[2*q], pb = acc1[2*q+1];
            *reinterpret_cast<float4*>(out + (size_t)r1 * OC + cgi * 16 + 4 * q) =
                make_float4(__uint_as_float((unsigned int)pa) * m1,
                            __uint_as_float((unsigned int)(pa >> 32)) * m1,
                            __uint_as_float((unsigned int)pb) * m1,
                            __uint_as_float((unsigned int)(pb >> 32)) * m1);
        }
    }
}

extern "C" void kernel_launch(void* const* d_in, const int* in_sizes, int n_in,
                              void* d_out, int out_size)
{
    // metadata order: x, edge_index, edge_attr, W, W_edge, a
    const float* x   = (const float*)d_in[0];
    const void*  ei  = d_in[1];                 // int64 or int32 [2, E], detected on device
    const float* W   = (const float*)d_in[3];   // [128, 64] row-major
    float*       out = (float*)d_out;

    const int n  = in_sizes[0] / IN_CH;   // 100000
    const int ne = in_sizes[1] / 2;       // 1600000

    const long long* col64 = (const long long*)ei + ne;
    const int*       col32 = (const int*)ei + ne;

    k_detect      <<<1, 32>>>((const unsigned int*)ei);
    k_zero_mask   <<<(n  + 255) / 256, 256>>>(n);
    k_scatter_mask<<<(ne + 255) / 256, 256>>>(col64, col32, ne, n);
    k_gemm_mask   <<<(n + BM - 1) / BM, 256>>>(x, W, out, n);
}